// round 5
// baseline (speedup 1.0000x reference)
#include <cuda_runtime.h>
#include <cstdint>

#define Nn 100000
#define Ee 3200000
#define F_IN 128
#define H1 64
#define H2 32
#define NC 10
#define SCAN_B 1024
#define NB_SCAN ((Nn + SCAN_B - 1) / SCAN_B)

struct __align__(8) EdgeW { int s; float w; };

// ---- scratch (static device globals; no allocation) ----
__device__ int    g_is64;
__device__ int    d_deg[Nn];
__device__ int    d_rowptr[Nn];
__device__ int    d_cursor[Nn];
__device__ float  d_dinv[Nn];
__device__ EdgeW  d_edges[Ee];          // CSR-sorted (src, norm)
__device__ int    d_blocksums[256];
__device__ float  d_h1[(size_t)Nn * H1];
__device__ float  d_out1[(size_t)Nn * H1];
__device__ float  d_h2[(size_t)Nn * H2];

// ---------------------------------------------------------------------------
__global__ void k_zero_deg() {
    int i = blockIdx.x * blockDim.x + threadIdx.x;
    if (i < Nn) d_deg[i] = 0;
}

// Detect whether edge_index is int64 (odd 32-bit words all zero) or int32.
__global__ void k_detect(const int* __restrict__ ei) {
    int any = 0;
    for (int i = threadIdx.x; i < 128; i += 32)
        if (ei[2 * i + 1] != 0) any = 1;
    unsigned b = __ballot_sync(0xFFFFFFFFu, any);
    if (threadIdx.x == 0) g_is64 = (b == 0) ? 1 : 0;
}

__device__ __forceinline__ int load_dst(const void* ei, int is64, int e) {
    if (is64) return (int)((const long long*)ei)[(size_t)Ee + e];
    return ((const int*)ei)[(size_t)Ee + e];
}
__device__ __forceinline__ int load_src(const void* ei, int is64, int e) {
    if (is64) return (int)((const long long*)ei)[e];
    return ((const int*)ei)[e];
}

// Histogram degrees on dst (src half never touched here).
__global__ void k_deg(const void* __restrict__ ei) {
    int is64 = g_is64;
    int stride = gridDim.x * blockDim.x;
    for (int e = blockIdx.x * blockDim.x + threadIdx.x; e < Ee; e += stride) {
        atomicAdd(&d_deg[load_dst(ei, is64, e)], 1);
    }
}

// Block-level exclusive scan of deg (Hillis-Steele), block totals out.
__global__ void k_scan1() {
    __shared__ int sd[SCAN_B];
    int tid = threadIdx.x;
    int i = blockIdx.x * SCAN_B + tid;
    int v = (i < Nn) ? d_deg[i] : 0;
    sd[tid] = v;
    __syncthreads();
    #pragma unroll
    for (int off = 1; off < SCAN_B; off <<= 1) {
        int t = (tid >= off) ? sd[tid - off] : 0;
        __syncthreads();
        sd[tid] += t;
        __syncthreads();
    }
    if (i < Nn) d_rowptr[i] = sd[tid] - v;     // exclusive within block
    if (tid == SCAN_B - 1) d_blocksums[blockIdx.x] = sd[tid];
}

__global__ void k_scan2() {
    int run = 0;
    for (int b = 0; b < NB_SCAN; b++) {
        int t = d_blocksums[b];
        d_blocksums[b] = run;
        run += t;
    }
}

__global__ void k_scan3() {
    int i = blockIdx.x * blockDim.x + threadIdx.x;
    if (i >= Nn) return;
    int rp = d_rowptr[i] + d_blocksums[i >> 10];
    d_rowptr[i] = rp;
    d_cursor[i] = rp;
    d_dinv[i] = rsqrtf((float)d_deg[i] + 1.0f);
}

// Scatter edges into CSR slots, storing (src, dinv[s]*dinv[d]) as 8B.
__global__ void k_scatter(const void* __restrict__ ei) {
    int is64 = g_is64;
    int stride = gridDim.x * blockDim.x;
    for (int e = blockIdx.x * blockDim.x + threadIdx.x; e < Ee; e += stride) {
        int s = load_src(ei, is64, e);
        int d = load_dst(ei, is64, e);
        int p = atomicAdd(&d_cursor[d], 1);
        EdgeW ew;
        ew.s = s;
        ew.w = d_dinv[s] * d_dinv[d];
        d_edges[p] = ew;
    }
}

// ---------------------------------------------------------------------------
// GEMM1: h1[N,64] = X[N,128] @ W1[128,64]   (64-row x 64-col tiles, 4x4/thread)
__global__ __launch_bounds__(256) void k_gemm1(const float* __restrict__ X,
                                               const float* __restrict__ W1) {
    __shared__ float sW[64 * 64];       // [k][c], k-chunk of 64
    __shared__ float sX[64 * 68];       // xT: [k][r], pitch 68
    int tid = threadIdx.x;
    int row0 = blockIdx.x * 64;
    int cidx = tid & 15;                // c0 = cidx*4
    int ridx = tid >> 4;                // r0 = ridx*4
    float acc[4][4] = {};

    for (int k0 = 0; k0 < 128; k0 += 64) {
        for (int i = tid; i < 64 * 64; i += 256) {
            int k = i >> 6, c = i & 63;
            sW[i] = W1[(size_t)(k0 + k) * 64 + c];
        }
        for (int i = tid; i < 64 * 64; i += 256) {
            int r = i >> 6, k = i & 63;
            int row = row0 + r;
            sX[k * 68 + r] = (row < Nn) ? X[(size_t)row * 128 + k0 + k] : 0.f;
        }
        __syncthreads();
        #pragma unroll
        for (int k = 0; k < 64; k++) {
            float4 w = *(const float4*)&sW[k * 64 + cidx * 4];
            float4 x = *(const float4*)&sX[k * 68 + ridx * 4];
            acc[0][0] += x.x * w.x; acc[0][1] += x.x * w.y; acc[0][2] += x.x * w.z; acc[0][3] += x.x * w.w;
            acc[1][0] += x.y * w.x; acc[1][1] += x.y * w.y; acc[1][2] += x.y * w.z; acc[1][3] += x.y * w.w;
            acc[2][0] += x.z * w.x; acc[2][1] += x.z * w.y; acc[2][2] += x.z * w.z; acc[2][3] += x.z * w.w;
            acc[3][0] += x.w * w.x; acc[3][1] += x.w * w.y; acc[3][2] += x.w * w.z; acc[3][3] += x.w * w.w;
        }
        __syncthreads();
    }
    #pragma unroll
    for (int rr = 0; rr < 4; rr++) {
        int row = row0 + ridx * 4 + rr;
        if (row < Nn) {
            float4 o = make_float4(acc[rr][0], acc[rr][1], acc[rr][2], acc[rr][3]);
            *(float4*)&d_h1[(size_t)row * 64 + cidx * 4] = o;
        }
    }
}

// Aggregation layer 1 (warp per node) + self-loop + bias + ReLU -> d_out1
// float2 per lane: 32 lanes x 2 floats = 64 features, one LDG.64 per edge/lane.
__global__ __launch_bounds__(256) void k_agg1(const float* __restrict__ b1) {
    int warp = (blockIdx.x * blockDim.x + threadIdx.x) >> 5;
    int lane = threadIdx.x & 31;
    if (warp >= Nn) return;
    int n = warp;
    int start = d_rowptr[n];
    int end = start + d_deg[n];
    const float2* __restrict__ h = (const float2*)d_h1;   // row stride 32 float2
    float2 a = make_float2(0.f, 0.f);
    int j = start;
    for (; j + 4 <= end; j += 4) {
        EdgeW e0 = d_edges[j], e1 = d_edges[j + 1], e2 = d_edges[j + 2], e3 = d_edges[j + 3];
        float2 v0 = h[(size_t)e0.s * 32 + lane];
        float2 v1 = h[(size_t)e1.s * 32 + lane];
        float2 v2 = h[(size_t)e2.s * 32 + lane];
        float2 v3 = h[(size_t)e3.s * 32 + lane];
        a.x += v0.x * e0.w;  a.y += v0.y * e0.w;
        a.x += v1.x * e1.w;  a.y += v1.y * e1.w;
        a.x += v2.x * e2.w;  a.y += v2.y * e2.w;
        a.x += v3.x * e3.w;  a.y += v3.y * e3.w;
    }
    for (; j < end; j++) {
        EdgeW e = d_edges[j];
        float2 v = h[(size_t)e.s * 32 + lane];
        a.x += v.x * e.w;
        a.y += v.y * e.w;
    }
    float di = d_dinv[n];
    float sl = di * di;
    float2 vs = h[(size_t)n * 32 + lane];
    a.x += vs.x * sl;   a.y += vs.y * sl;
    float2 bb = ((const float2*)b1)[lane];
    a.x = fmaxf(a.x + bb.x, 0.f);
    a.y = fmaxf(a.y + bb.y, 0.f);
    ((float2*)d_out1)[(size_t)n * 32 + lane] = a;
}

// GEMM2: h2[N,32] = out1[N,64] @ W2[64,32]  (128-row x 32-col tiles, 4x4/thread)
__global__ __launch_bounds__(256) void k_gemm2(const float* __restrict__ W2) {
    __shared__ float sW[64 * 32];
    __shared__ float sX[64 * 132];      // xT: [k][r], pitch 132
    int tid = threadIdx.x;
    int row0 = blockIdx.x * 128;
    int cidx = tid & 7;                 // c0 = cidx*4
    int ridx = tid >> 3;                // r0 = ridx*4 (0..124)
    float acc[4][4] = {};

    for (int i = tid; i < 64 * 32; i += 256) sW[i] = W2[i];
    for (int i = tid; i < 128 * 64; i += 256) {
        int r = i >> 6, k = i & 63;
        int row = row0 + r;
        sX[k * 132 + r] = (row < Nn) ? d_out1[(size_t)row * 64 + k] : 0.f;
    }
    __syncthreads();
    #pragma unroll
    for (int k = 0; k < 64; k++) {
        float4 w = *(const float4*)&sW[k * 32 + cidx * 4];
        float4 x = *(const float4*)&sX[k * 132 + ridx * 4];
        acc[0][0] += x.x * w.x; acc[0][1] += x.x * w.y; acc[0][2] += x.x * w.z; acc[0][3] += x.x * w.w;
        acc[1][0] += x.y * w.x; acc[1][1] += x.y * w.y; acc[1][2] += x.y * w.z; acc[1][3] += x.y * w.w;
        acc[2][0] += x.z * w.x; acc[2][1] += x.z * w.y; acc[2][2] += x.z * w.z; acc[2][3] += x.z * w.w;
        acc[3][0] += x.w * w.x; acc[3][1] += x.w * w.y; acc[3][2] += x.w * w.z; acc[3][3] += x.w * w.w;
    }
    #pragma unroll
    for (int rr = 0; rr < 4; rr++) {
        int row = row0 + ridx * 4 + rr;
        if (row < Nn) {
            float4 o = make_float4(acc[rr][0], acc[rr][1], acc[rr][2], acc[rr][3]);
            *(float4*)&d_h2[(size_t)row * 32 + cidx * 4] = o;
        }
    }
}

// Aggregation layer 2 + bias + ReLU + classifier GEMV + log_softmax (warp/node)
__global__ __launch_bounds__(256) void k_final(const float* __restrict__ b2,
                                               const float* __restrict__ Wc,
                                               const float* __restrict__ bc,
                                               float* __restrict__ out) {
    __shared__ float sWc[32 * NC];
    __shared__ float sb2[32];
    __shared__ float sbc[16];
    int tid = threadIdx.x;
    for (int i = tid; i < 32 * NC; i += 256) sWc[i] = Wc[i];
    if (tid < 32) sb2[tid] = b2[tid];
    if (tid < NC) sbc[tid] = bc[tid];
    __syncthreads();

    int warp = (blockIdx.x * blockDim.x + tid) >> 5;
    int lane = tid & 31;
    if (warp >= Nn) return;
    int n = warp;
    int start = d_rowptr[n];
    int end = start + d_deg[n];
    const float* __restrict__ h = d_h2;
    float acc = 0.f;
    int j = start;
    for (; j + 4 <= end; j += 4) {
        EdgeW e0 = d_edges[j], e1 = d_edges[j + 1], e2 = d_edges[j + 2], e3 = d_edges[j + 3];
        acc += h[(size_t)e0.s * 32 + lane] * e0.w;
        acc += h[(size_t)e1.s * 32 + lane] * e1.w;
        acc += h[(size_t)e2.s * 32 + lane] * e2.w;
        acc += h[(size_t)e3.s * 32 + lane] * e3.w;
    }
    for (; j < end; j++) {
        EdgeW e = d_edges[j];
        acc += h[(size_t)e.s * 32 + lane] * e.w;
    }
    float di = d_dinv[n];
    acc += h[(size_t)n * 32 + lane] * (di * di);
    acc += sb2[lane];
    float v = fmaxf(acc, 0.f);

    float p[NC];
    #pragma unroll
    for (int c = 0; c < NC; c++) p[c] = v * sWc[lane * NC + c];
    #pragma unroll
    for (int off = 16; off >= 1; off >>= 1) {
        #pragma unroll
        for (int c = 0; c < NC; c++)
            p[c] += __shfl_xor_sync(0xFFFFFFFFu, p[c], off);
    }
    #pragma unroll
    for (int c = 0; c < NC; c++) p[c] += sbc[c];

    float m = p[0];
    #pragma unroll
    for (int c = 1; c < NC; c++) m = fmaxf(m, p[c]);
    float s = 0.f;
    #pragma unroll
    for (int c = 0; c < NC; c++) s += expf(p[c] - m);
    float lse = m + logf(s);
    if (lane < NC) out[(size_t)n * NC + lane] = p[lane] - lse;
}

// ---------------------------------------------------------------------------
extern "C" void kernel_launch(void* const* d_in, const int* in_sizes, int n_in,
                              void* d_out, int out_size) {
    const float* x  = (const float*)d_in[0];
    const void*  ei = d_in[1];
    const float* W1 = (const float*)d_in[2];
    const float* b1 = (const float*)d_in[3];
    const float* W2 = (const float*)d_in[4];
    const float* b2 = (const float*)d_in[5];
    const float* Wc = (const float*)d_in[6];
    const float* bc = (const float*)d_in[7];
    float* out = (float*)d_out;

    // ---- graph build (CSR via counting sort) ----
    k_zero_deg<<<(Nn + 255) / 256, 256>>>();
    k_detect<<<1, 32>>>((const int*)ei);
    k_deg<<<(Ee + 255) / 256, 256>>>(ei);
    k_scan1<<<NB_SCAN, SCAN_B>>>();
    k_scan2<<<1, 1>>>();
    k_scan3<<<(Nn + 255) / 256, 256>>>();
    k_scatter<<<(Ee + 255) / 256, 256>>>(ei);

    // ---- layer 1 ----
    k_gemm1<<<(Nn + 63) / 64, 256>>>(x, W1);
    k_agg1<<<(Nn + 7) / 8, 256>>>(b1);

    // ---- layer 2 + classifier ----
    k_gemm2<<<(Nn + 127) / 128, 256>>>(W2);
    k_final<<<(Nn + 7) / 8, 256>>>(b2, Wc, bc, out);
}

// round 6
// speedup vs baseline: 1.0709x; 1.0709x over previous
#include <cuda_runtime.h>
#include <cuda_fp16.h>
#include <cstdint>

#define Nn 100000
#define Ee 3200000
#define F_IN 128
#define H1 64
#define H2 32
#define NC 10
#define SCAN_B 1024
#define NB_SCAN ((Nn + SCAN_B - 1) / SCAN_B)

struct __align__(8) EdgeW { int s; float w; };

// ---- scratch (static device globals; no allocation) ----
__device__ int    g_is64;
__device__ int    d_deg[Nn];
__device__ int    d_rowptr[Nn];
__device__ int    d_cursor[Nn];
__device__ float  d_dinv[Nn];
__device__ EdgeW  d_edges[Ee];              // CSR-sorted (src, norm)
__device__ int    d_blocksums[128];
__device__ __half d_h1[(size_t)Nn * H1];    // XW1 in fp16 (gather payload)
__device__ float  d_out1[(size_t)Nn * H1];  // post-agg1 (fp32, GEMM2 input)
__device__ __half d_h2[(size_t)Nn * H2];    // out1W2 in fp16 (gather payload)

// ---------------------------------------------------------------------------
__global__ void k_zero_deg() {
    int i = blockIdx.x * blockDim.x + threadIdx.x;
    if (i < Nn) d_deg[i] = 0;
}

// Detect whether edge_index is int64 (odd 32-bit words all zero) or int32.
__global__ void k_detect(const int* __restrict__ ei) {
    int any = 0;
    for (int i = threadIdx.x; i < 128; i += 32)
        if (ei[2 * i + 1] != 0) any = 1;
    unsigned b = __ballot_sync(0xFFFFFFFFu, any);
    if (threadIdx.x == 0) g_is64 = (b == 0) ? 1 : 0;
}

__device__ __forceinline__ int load_dst(const void* ei, int is64, int e) {
    if (is64) return (int)((const long long*)ei)[(size_t)Ee + e];
    return ((const int*)ei)[(size_t)Ee + e];
}
__device__ __forceinline__ int load_src(const void* ei, int is64, int e) {
    if (is64) return (int)((const long long*)ei)[e];
    return ((const int*)ei)[e];
}

// Histogram degrees on dst (src half never touched here).
__global__ void k_deg(const void* __restrict__ ei) {
    int is64 = g_is64;
    int stride = gridDim.x * blockDim.x;
    for (int e = blockIdx.x * blockDim.x + threadIdx.x; e < Ee; e += stride) {
        atomicAdd(&d_deg[load_dst(ei, is64, e)], 1);
    }
}

// Block-level exclusive scan of deg (Hillis-Steele), block totals out.
__global__ void k_scan1() {
    __shared__ int sd[SCAN_B];
    int tid = threadIdx.x;
    int i = blockIdx.x * SCAN_B + tid;
    int v = (i < Nn) ? d_deg[i] : 0;
    sd[tid] = v;
    __syncthreads();
    #pragma unroll
    for (int off = 1; off < SCAN_B; off <<= 1) {
        int t = (tid >= off) ? sd[tid - off] : 0;
        __syncthreads();
        sd[tid] += t;
        __syncthreads();
    }
    if (i < Nn) d_rowptr[i] = sd[tid] - v;     // exclusive within block
    if (tid == SCAN_B - 1) d_blocksums[blockIdx.x] = sd[tid];
}

// Parallel exclusive scan of the 98 block sums (one 128-thread block).
__global__ void k_scan2() {
    __shared__ int sd[128];
    int tid = threadIdx.x;
    int v = (tid < NB_SCAN) ? d_blocksums[tid] : 0;
    sd[tid] = v;
    __syncthreads();
    #pragma unroll
    for (int off = 1; off < 128; off <<= 1) {
        int t = (tid >= off) ? sd[tid - off] : 0;
        __syncthreads();
        sd[tid] += t;
        __syncthreads();
    }
    if (tid < NB_SCAN) d_blocksums[tid] = sd[tid] - v;   // exclusive
}

__global__ void k_scan3() {
    int i = blockIdx.x * blockDim.x + threadIdx.x;
    if (i >= Nn) return;
    int rp = d_rowptr[i] + d_blocksums[i >> 10];
    d_rowptr[i] = rp;
    d_cursor[i] = rp;
    d_dinv[i] = rsqrtf((float)d_deg[i] + 1.0f);
}

// Scatter edges into CSR slots, storing (src, dinv[s]*dinv[d]) as 8B.
__global__ void k_scatter(const void* __restrict__ ei) {
    int is64 = g_is64;
    int stride = gridDim.x * blockDim.x;
    for (int e = blockIdx.x * blockDim.x + threadIdx.x; e < Ee; e += stride) {
        int s = load_src(ei, is64, e);
        int d = load_dst(ei, is64, e);
        int p = atomicAdd(&d_cursor[d], 1);
        EdgeW ew;
        ew.s = s;
        ew.w = d_dinv[s] * d_dinv[d];
        d_edges[p] = ew;
    }
}

// ---------------------------------------------------------------------------
// GEMM1: h1[N,64] = X[N,128] @ W1[128,64], epilogue stores fp16.
__global__ __launch_bounds__(256) void k_gemm1(const float* __restrict__ X,
                                               const float* __restrict__ W1) {
    __shared__ float sW[64 * 64];       // [k][c], k-chunk of 64
    __shared__ float sX[64 * 68];       // xT: [k][r], pitch 68
    int tid = threadIdx.x;
    int row0 = blockIdx.x * 64;
    int cidx = tid & 15;                // c0 = cidx*4
    int ridx = tid >> 4;                // r0 = ridx*4
    float acc[4][4] = {};

    for (int k0 = 0; k0 < 128; k0 += 64) {
        for (int i = tid; i < 64 * 64; i += 256) {
            int k = i >> 6, c = i & 63;
            sW[i] = W1[(size_t)(k0 + k) * 64 + c];
        }
        for (int i = tid; i < 64 * 64; i += 256) {
            int r = i >> 6, k = i & 63;
            int row = row0 + r;
            sX[k * 68 + r] = (row < Nn) ? X[(size_t)row * 128 + k0 + k] : 0.f;
        }
        __syncthreads();
        #pragma unroll
        for (int k = 0; k < 64; k++) {
            float4 w = *(const float4*)&sW[k * 64 + cidx * 4];
            float4 x = *(const float4*)&sX[k * 68 + ridx * 4];
            acc[0][0] += x.x * w.x; acc[0][1] += x.x * w.y; acc[0][2] += x.x * w.z; acc[0][3] += x.x * w.w;
            acc[1][0] += x.y * w.x; acc[1][1] += x.y * w.y; acc[1][2] += x.y * w.z; acc[1][3] += x.y * w.w;
            acc[2][0] += x.z * w.x; acc[2][1] += x.z * w.y; acc[2][2] += x.z * w.z; acc[2][3] += x.z * w.w;
            acc[3][0] += x.w * w.x; acc[3][1] += x.w * w.y; acc[3][2] += x.w * w.z; acc[3][3] += x.w * w.w;
        }
        __syncthreads();
    }
    #pragma unroll
    for (int rr = 0; rr < 4; rr++) {
        int row = row0 + ridx * 4 + rr;
        if (row < Nn) {
            __half2 p0 = __floats2half2_rn(acc[rr][0], acc[rr][1]);
            __half2 p1 = __floats2half2_rn(acc[rr][2], acc[rr][3]);
            __half2* dst = (__half2*)&d_h1[(size_t)row * 64 + cidx * 4];
            dst[0] = p0;
            dst[1] = p1;
        }
    }
}

// Aggregation layer 1 (warp per node) + self-loop + bias + ReLU -> d_out1
// fp16 messages: lane reads one half2 (4B); warp covers the 64-feat row = 128B.
__global__ __launch_bounds__(256) void k_agg1(const float* __restrict__ b1) {
    int warp = (blockIdx.x * blockDim.x + threadIdx.x) >> 5;
    int lane = threadIdx.x & 31;
    if (warp >= Nn) return;
    int n = warp;
    int start = d_rowptr[n];
    int end = start + d_deg[n];
    const __half2* __restrict__ h = (const __half2*)d_h1;   // row stride 32 half2
    float ax = 0.f, ay = 0.f;
    int j = start;
    for (; j + 4 <= end; j += 4) {
        EdgeW e0 = d_edges[j], e1 = d_edges[j + 1], e2 = d_edges[j + 2], e3 = d_edges[j + 3];
        float2 v0 = __half22float2(h[(size_t)e0.s * 32 + lane]);
        float2 v1 = __half22float2(h[(size_t)e1.s * 32 + lane]);
        float2 v2 = __half22float2(h[(size_t)e2.s * 32 + lane]);
        float2 v3 = __half22float2(h[(size_t)e3.s * 32 + lane]);
        ax += v0.x * e0.w;  ay += v0.y * e0.w;
        ax += v1.x * e1.w;  ay += v1.y * e1.w;
        ax += v2.x * e2.w;  ay += v2.y * e2.w;
        ax += v3.x * e3.w;  ay += v3.y * e3.w;
    }
    for (; j < end; j++) {
        EdgeW e = d_edges[j];
        float2 v = __half22float2(h[(size_t)e.s * 32 + lane]);
        ax += v.x * e.w;
        ay += v.y * e.w;
    }
    float di = d_dinv[n];
    float sl = di * di;
    float2 vs = __half22float2(h[(size_t)n * 32 + lane]);
    ax += vs.x * sl;   ay += vs.y * sl;
    float2 bb = ((const float2*)b1)[lane];
    float2 o;
    o.x = fmaxf(ax + bb.x, 0.f);
    o.y = fmaxf(ay + bb.y, 0.f);
    ((float2*)d_out1)[(size_t)n * 32 + lane] = o;
}

// GEMM2: h2[N,32] = out1[N,64] @ W2[64,32], epilogue stores fp16.
__global__ __launch_bounds__(256) void k_gemm2(const float* __restrict__ W2) {
    __shared__ float sW[64 * 32];
    __shared__ float sX[64 * 132];      // xT: [k][r], pitch 132
    int tid = threadIdx.x;
    int row0 = blockIdx.x * 128;
    int cidx = tid & 7;                 // c0 = cidx*4
    int ridx = tid >> 3;                // r0 = ridx*4 (0..124)
    float acc[4][4] = {};

    for (int i = tid; i < 64 * 32; i += 256) sW[i] = W2[i];
    for (int i = tid; i < 128 * 64; i += 256) {
        int r = i >> 6, k = i & 63;
        int row = row0 + r;
        sX[k * 132 + r] = (row < Nn) ? d_out1[(size_t)row * 64 + k] : 0.f;
    }
    __syncthreads();
    #pragma unroll
    for (int k = 0; k < 64; k++) {
        float4 w = *(const float4*)&sW[k * 32 + cidx * 4];
        float4 x = *(const float4*)&sX[k * 132 + ridx * 4];
        acc[0][0] += x.x * w.x; acc[0][1] += x.x * w.y; acc[0][2] += x.x * w.z; acc[0][3] += x.x * w.w;
        acc[1][0] += x.y * w.x; acc[1][1] += x.y * w.y; acc[1][2] += x.y * w.z; acc[1][3] += x.y * w.w;
        acc[2][0] += x.z * w.x; acc[2][1] += x.z * w.y; acc[2][2] += x.z * w.z; acc[2][3] += x.z * w.w;
        acc[3][0] += x.w * w.x; acc[3][1] += x.w * w.y; acc[3][2] += x.w * w.z; acc[3][3] += x.w * w.w;
    }
    #pragma unroll
    for (int rr = 0; rr < 4; rr++) {
        int row = row0 + ridx * 4 + rr;
        if (row < Nn) {
            __half2 p0 = __floats2half2_rn(acc[rr][0], acc[rr][1]);
            __half2 p1 = __floats2half2_rn(acc[rr][2], acc[rr][3]);
            __half2* dst = (__half2*)&d_h2[(size_t)row * 32 + cidx * 4];
            dst[0] = p0;
            dst[1] = p1;
        }
    }
}

// Aggregation layer 2 + bias + ReLU + classifier GEMV + log_softmax (warp/node)
__global__ __launch_bounds__(256) void k_final(const float* __restrict__ b2,
                                               const float* __restrict__ Wc,
                                               const float* __restrict__ bc,
                                               float* __restrict__ out) {
    __shared__ float sWc[32 * NC];
    __shared__ float sb2[32];
    __shared__ float sbc[16];
    int tid = threadIdx.x;
    for (int i = tid; i < 32 * NC; i += 256) sWc[i] = Wc[i];
    if (tid < 32) sb2[tid] = b2[tid];
    if (tid < NC) sbc[tid] = bc[tid];
    __syncthreads();

    int warp = (blockIdx.x * blockDim.x + tid) >> 5;
    int lane = tid & 31;
    if (warp >= Nn) return;
    int n = warp;
    int start = d_rowptr[n];
    int end = start + d_deg[n];
    const __half* __restrict__ h = d_h2;
    float acc = 0.f;
    int j = start;
    for (; j + 4 <= end; j += 4) {
        EdgeW e0 = d_edges[j], e1 = d_edges[j + 1], e2 = d_edges[j + 2], e3 = d_edges[j + 3];
        acc += __half2float(h[(size_t)e0.s * 32 + lane]) * e0.w;
        acc += __half2float(h[(size_t)e1.s * 32 + lane]) * e1.w;
        acc += __half2float(h[(size_t)e2.s * 32 + lane]) * e2.w;
        acc += __half2float(h[(size_t)e3.s * 32 + lane]) * e3.w;
    }
    for (; j < end; j++) {
        EdgeW e = d_edges[j];
        acc += __half2float(h[(size_t)e.s * 32 + lane]) * e.w;
    }
    float di = d_dinv[n];
    acc += __half2float(h[(size_t)n * 32 + lane]) * (di * di);
    acc += sb2[lane];
    float v = fmaxf(acc, 0.f);

    float p[NC];
    #pragma unroll
    for (int c = 0; c < NC; c++) p[c] = v * sWc[lane * NC + c];
    #pragma unroll
    for (int off = 16; off >= 1; off >>= 1) {
        #pragma unroll
        for (int c = 0; c < NC; c++)
            p[c] += __shfl_xor_sync(0xFFFFFFFFu, p[c], off);
    }
    #pragma unroll
    for (int c = 0; c < NC; c++) p[c] += sbc[c];

    float m = p[0];
    #pragma unroll
    for (int c = 1; c < NC; c++) m = fmaxf(m, p[c]);
    float s = 0.f;
    #pragma unroll
    for (int c = 0; c < NC; c++) s += expf(p[c] - m);
    float lse = m + logf(s);
    if (lane < NC) out[(size_t)n * NC + lane] = p[lane] - lse;
}

// ---------------------------------------------------------------------------
extern "C" void kernel_launch(void* const* d_in, const int* in_sizes, int n_in,
                              void* d_out, int out_size) {
    const float* x  = (const float*)d_in[0];
    const void*  ei = d_in[1];
    const float* W1 = (const float*)d_in[2];
    const float* b1 = (const float*)d_in[3];
    const float* W2 = (const float*)d_in[4];
    const float* b2 = (const float*)d_in[5];
    const float* Wc = (const float*)d_in[6];
    const float* bc = (const float*)d_in[7];
    float* out = (float*)d_out;

    // ---- graph build (CSR via counting sort) ----
    k_zero_deg<<<(Nn + 255) / 256, 256>>>();
    k_detect<<<1, 32>>>((const int*)ei);
    k_deg<<<(Ee + 255) / 256, 256>>>(ei);
    k_scan1<<<NB_SCAN, SCAN_B>>>();
    k_scan2<<<1, 128>>>();
    k_scan3<<<(Nn + 255) / 256, 256>>>();
    k_scatter<<<(Ee + 255) / 256, 256>>>(ei);

    // ---- layer 1 ----
    k_gemm1<<<(Nn + 63) / 64, 256>>>(x, W1);
    k_agg1<<<(Nn + 7) / 8, 256>>>(b1);

    // ---- layer 2 + classifier ----
    k_gemm2<<<(Nn + 127) / 128, 256>>>(W2);
    k_final<<<(Nn + 7) / 8, 256>>>(b2, Wc, bc, out);
}

// round 7
// speedup vs baseline: 1.0810x; 1.0095x over previous
#include <cuda_runtime.h>
#include <cuda_fp16.h>
#include <cstdint>

#define Nn 100000
#define Ee 3200000
#define F_IN 128
#define H1 64
#define H2 32
#define NC 10
#define SCAN_B 1024
#define NB_SCAN ((Nn + SCAN_B - 1) / SCAN_B)
#define FULLM 0xFFFFFFFFu

struct __align__(8) EdgeW { int s; float w; };

// ---- scratch (static device globals; no allocation) ----
__device__ int    g_is64;
__device__ int    d_deg[Nn];
__device__ int    d_rowptr[Nn];
__device__ int    d_cursor[Nn];
__device__ float  d_dinv[Nn];
__device__ EdgeW  d_edges[Ee];              // CSR-sorted (src, norm)
__device__ int    d_blocksums[128];
__device__ __half d_h1[(size_t)Nn * H1];    // XW1 in fp16 (gather payload)
__device__ float  d_out1[(size_t)Nn * H1];  // post-agg1 (fp32, GEMM2 input)
__device__ __half d_h2[(size_t)Nn * H2];    // out1W2 in fp16 (gather payload)

// ---------------------------------------------------------------------------
__global__ void k_zero_deg() {
    int i = blockIdx.x * blockDim.x + threadIdx.x;
    if (i < Nn) d_deg[i] = 0;
}

// Detect whether edge_index is int64 (odd 32-bit words all zero) or int32.
__global__ void k_detect(const int* __restrict__ ei) {
    int any = 0;
    for (int i = threadIdx.x; i < 128; i += 32)
        if (ei[2 * i + 1] != 0) any = 1;
    unsigned b = __ballot_sync(FULLM, any);
    if (threadIdx.x == 0) g_is64 = (b == 0) ? 1 : 0;
}

__device__ __forceinline__ int load_dst(const void* ei, int is64, int e) {
    if (is64) return (int)((const long long*)ei)[(size_t)Ee + e];
    return ((const int*)ei)[(size_t)Ee + e];
}
__device__ __forceinline__ int load_src(const void* ei, int is64, int e) {
    if (is64) return (int)((const long long*)ei)[e];
    return ((const int*)ei)[e];
}

// Histogram degrees on dst (src half never touched here).
__global__ void k_deg(const void* __restrict__ ei) {
    int is64 = g_is64;
    int stride = gridDim.x * blockDim.x;
    for (int e = blockIdx.x * blockDim.x + threadIdx.x; e < Ee; e += stride) {
        atomicAdd(&d_deg[load_dst(ei, is64, e)], 1);
    }
}

// Block-level exclusive scan of deg (Hillis-Steele), block totals out.
__global__ void k_scan1() {
    __shared__ int sd[SCAN_B];
    int tid = threadIdx.x;
    int i = blockIdx.x * SCAN_B + tid;
    int v = (i < Nn) ? d_deg[i] : 0;
    sd[tid] = v;
    __syncthreads();
    #pragma unroll
    for (int off = 1; off < SCAN_B; off <<= 1) {
        int t = (tid >= off) ? sd[tid - off] : 0;
        __syncthreads();
        sd[tid] += t;
        __syncthreads();
    }
    if (i < Nn) d_rowptr[i] = sd[tid] - v;     // exclusive within block
    if (tid == SCAN_B - 1) d_blocksums[blockIdx.x] = sd[tid];
}

// Parallel exclusive scan of the 98 block sums (one 128-thread block).
__global__ void k_scan2() {
    __shared__ int sd[128];
    int tid = threadIdx.x;
    int v = (tid < NB_SCAN) ? d_blocksums[tid] : 0;
    sd[tid] = v;
    __syncthreads();
    #pragma unroll
    for (int off = 1; off < 128; off <<= 1) {
        int t = (tid >= off) ? sd[tid - off] : 0;
        __syncthreads();
        sd[tid] += t;
        __syncthreads();
    }
    if (tid < NB_SCAN) d_blocksums[tid] = sd[tid] - v;   // exclusive
}

__global__ void k_scan3() {
    int i = blockIdx.x * blockDim.x + threadIdx.x;
    if (i >= Nn) return;
    int rp = d_rowptr[i] + d_blocksums[i >> 10];
    d_rowptr[i] = rp;
    d_cursor[i] = rp;
    d_dinv[i] = rsqrtf((float)d_deg[i] + 1.0f);
}

// Scatter edges into CSR slots, storing (src, dinv[s]*dinv[d]) as 8B.
__global__ void k_scatter(const void* __restrict__ ei) {
    int is64 = g_is64;
    int stride = gridDim.x * blockDim.x;
    for (int e = blockIdx.x * blockDim.x + threadIdx.x; e < Ee; e += stride) {
        int s = load_src(ei, is64, e);
        int d = load_dst(ei, is64, e);
        int p = atomicAdd(&d_cursor[d], 1);
        EdgeW ew;
        ew.s = s;
        ew.w = d_dinv[s] * d_dinv[d];
        d_edges[p] = ew;
    }
}

// ---------------------------------------------------------------------------
// GEMM1: h1[N,64] = X[N,128] @ W1[128,64], epilogue stores fp16.
__global__ __launch_bounds__(256) void k_gemm1(const float* __restrict__ X,
                                               const float* __restrict__ W1) {
    __shared__ float sW[64 * 64];       // [k][c], k-chunk of 64
    __shared__ float sX[64 * 68];       // xT: [k][r], pitch 68
    int tid = threadIdx.x;
    int row0 = blockIdx.x * 64;
    int cidx = tid & 15;                // c0 = cidx*4
    int ridx = tid >> 4;                // r0 = ridx*4
    float acc[4][4] = {};

    for (int k0 = 0; k0 < 128; k0 += 64) {
        for (int i = tid; i < 64 * 64; i += 256) {
            int k = i >> 6, c = i & 63;
            sW[i] = W1[(size_t)(k0 + k) * 64 + c];
        }
        for (int i = tid; i < 64 * 64; i += 256) {
            int r = i >> 6, k = i & 63;
            int row = row0 + r;
            sX[k * 68 + r] = (row < Nn) ? X[(size_t)row * 128 + k0 + k] : 0.f;
        }
        __syncthreads();
        #pragma unroll
        for (int k = 0; k < 64; k++) {
            float4 w = *(const float4*)&sW[k * 64 + cidx * 4];
            float4 x = *(const float4*)&sX[k * 68 + ridx * 4];
            acc[0][0] += x.x * w.x; acc[0][1] += x.x * w.y; acc[0][2] += x.x * w.z; acc[0][3] += x.x * w.w;
            acc[1][0] += x.y * w.x; acc[1][1] += x.y * w.y; acc[1][2] += x.y * w.z; acc[1][3] += x.y * w.w;
            acc[2][0] += x.z * w.x; acc[2][1] += x.z * w.y; acc[2][2] += x.z * w.z; acc[2][3] += x.z * w.w;
            acc[3][0] += x.w * w.x; acc[3][1] += x.w * w.y; acc[3][2] += x.w * w.z; acc[3][3] += x.w * w.w;
        }
        __syncthreads();
    }
    #pragma unroll
    for (int rr = 0; rr < 4; rr++) {
        int row = row0 + ridx * 4 + rr;
        if (row < Nn) {
            __half2 p0 = __floats2half2_rn(acc[rr][0], acc[rr][1]);
            __half2 p1 = __floats2half2_rn(acc[rr][2], acc[rr][3]);
            __half2* dst = (__half2*)&d_h1[(size_t)row * 64 + cidx * 4];
            dst[0] = p0;
            dst[1] = p1;
        }
    }
}

// Aggregation layer 1 (warp per node) + self-loop + bias + ReLU -> d_out1
// 16 lanes x 8B cover one 128B row -> 2 edges per gather LDG.
// Edge metadata loaded 32-at-a-time, broadcast via shfl.
__global__ __launch_bounds__(256) void k_agg1(const float* __restrict__ b1) {
    int warp = (blockIdx.x * blockDim.x + threadIdx.x) >> 5;
    int lane = threadIdx.x & 31;
    if (warp >= Nn) return;
    int n = warp;
    int start = d_rowptr[n];
    int end = start + d_deg[n];
    int half = lane >> 4;               // which edge of the pair
    int sub  = lane & 15;               // feature group (4 halves each)
    const __half* __restrict__ h = d_h1;
    float a0 = 0.f, a1 = 0.f, a2 = 0.f, a3 = 0.f;

    for (int base = start; base < end; base += 32) {
        int rem = end - base; if (rem > 32) rem = 32;
        int s_l = 0; float w_l = 0.f;
        if (lane < rem) { EdgeW ew = d_edges[base + lane]; s_l = ew.s; w_l = ew.w; }
        int npair = (rem + 1) >> 1;
        for (int p = 0; p < npair; p++) {
            int idx = 2 * p + half;
            int   s = __shfl_sync(FULLM, s_l, idx);
            float w = __shfl_sync(FULLM, w_l, idx);
            if (idx < rem) {
                uint2 raw = *(const uint2*)(h + (size_t)s * 64 + sub * 4);
                float2 lo = __half22float2(*(__half2*)&raw.x);
                float2 hi = __half22float2(*(__half2*)&raw.y);
                a0 += lo.x * w; a1 += lo.y * w; a2 += hi.x * w; a3 += hi.y * w;
            }
        }
    }
    // combine the two edge-halves; all lanes end with full sums
    a0 += __shfl_xor_sync(FULLM, a0, 16);
    a1 += __shfl_xor_sync(FULLM, a1, 16);
    a2 += __shfl_xor_sync(FULLM, a2, 16);
    a3 += __shfl_xor_sync(FULLM, a3, 16);

    if (half == 0) {
        float di = d_dinv[n];
        float sl = di * di;
        uint2 raw = *(const uint2*)(h + (size_t)n * 64 + sub * 4);
        float2 lo = __half22float2(*(__half2*)&raw.x);
        float2 hi = __half22float2(*(__half2*)&raw.y);
        a0 += lo.x * sl; a1 += lo.y * sl; a2 += hi.x * sl; a3 += hi.y * sl;
        float4 bb = ((const float4*)b1)[sub];
        float4 o;
        o.x = fmaxf(a0 + bb.x, 0.f);
        o.y = fmaxf(a1 + bb.y, 0.f);
        o.z = fmaxf(a2 + bb.z, 0.f);
        o.w = fmaxf(a3 + bb.w, 0.f);
        ((float4*)d_out1)[(size_t)n * 16 + sub] = o;
    }
}

// GEMM2: h2[N,32] = out1[N,64] @ W2[64,32], epilogue stores fp16.
__global__ __launch_bounds__(256) void k_gemm2(const float* __restrict__ W2) {
    __shared__ float sW[64 * 32];
    __shared__ float sX[64 * 132];      // xT: [k][r], pitch 132
    int tid = threadIdx.x;
    int row0 = blockIdx.x * 128;
    int cidx = tid & 7;                 // c0 = cidx*4
    int ridx = tid >> 3;                // r0 = ridx*4 (0..124)
    float acc[4][4] = {};

    for (int i = tid; i < 64 * 32; i += 256) sW[i] = W2[i];
    for (int i = tid; i < 128 * 64; i += 256) {
        int r = i >> 6, k = i & 63;
        int row = row0 + r;
        sX[k * 132 + r] = (row < Nn) ? d_out1[(size_t)row * 64 + k] : 0.f;
    }
    __syncthreads();
    #pragma unroll
    for (int k = 0; k < 64; k++) {
        float4 w = *(const float4*)&sW[k * 32 + cidx * 4];
        float4 x = *(const float4*)&sX[k * 132 + ridx * 4];
        acc[0][0] += x.x * w.x; acc[0][1] += x.x * w.y; acc[0][2] += x.x * w.z; acc[0][3] += x.x * w.w;
        acc[1][0] += x.y * w.x; acc[1][1] += x.y * w.y; acc[1][2] += x.y * w.z; acc[1][3] += x.y * w.w;
        acc[2][0] += x.z * w.x; acc[2][1] += x.z * w.y; acc[2][2] += x.z * w.z; acc[2][3] += x.z * w.w;
        acc[3][0] += x.w * w.x; acc[3][1] += x.w * w.y; acc[3][2] += x.w * w.z; acc[3][3] += x.w * w.w;
    }
    #pragma unroll
    for (int rr = 0; rr < 4; rr++) {
        int row = row0 + ridx * 4 + rr;
        if (row < Nn) {
            __half2 p0 = __floats2half2_rn(acc[rr][0], acc[rr][1]);
            __half2 p1 = __floats2half2_rn(acc[rr][2], acc[rr][3]);
            __half2* dst = (__half2*)&d_h2[(size_t)row * 32 + cidx * 4];
            dst[0] = p0;
            dst[1] = p1;
        }
    }
}

// Aggregation layer 2 + bias + ReLU + classifier GEMV + log_softmax (warp/node)
// 8 lanes x 8B cover one 64B row -> 4 edges per gather LDG.
__global__ __launch_bounds__(256) void k_final(const float* __restrict__ b2,
                                               const float* __restrict__ Wc,
                                               const float* __restrict__ bc,
                                               float* __restrict__ out) {
    __shared__ float sWc[32 * NC];
    __shared__ float sb2[32];
    __shared__ float sbc[16];
    int tid = threadIdx.x;
    for (int i = tid; i < 32 * NC; i += 256) sWc[i] = Wc[i];
    if (tid < 32) sb2[tid] = b2[tid];
    if (tid < NC) sbc[tid] = bc[tid];
    __syncthreads();

    int warp = (blockIdx.x * blockDim.x + tid) >> 5;
    int lane = tid & 31;
    if (warp >= Nn) return;
    int n = warp;
    int start = d_rowptr[n];
    int end = start + d_deg[n];
    int grp = lane >> 3;                // which of 4 edges
    int sub = lane & 7;                 // feature group (4 halves each)
    const __half* __restrict__ h = d_h2;
    float a0 = 0.f, a1 = 0.f, a2 = 0.f, a3 = 0.f;

    for (int base = start; base < end; base += 32) {
        int rem = end - base; if (rem > 32) rem = 32;
        int s_l = 0; float w_l = 0.f;
        if (lane < rem) { EdgeW ew = d_edges[base + lane]; s_l = ew.s; w_l = ew.w; }
        int ngrp = (rem + 3) >> 2;
        for (int p = 0; p < ngrp; p++) {
            int idx = 4 * p + grp;
            int   s = __shfl_sync(FULLM, s_l, idx);
            float w = __shfl_sync(FULLM, w_l, idx);
            if (idx < rem) {
                uint2 raw = *(const uint2*)(h + (size_t)s * 32 + sub * 4);
                float2 lo = __half22float2(*(__half2*)&raw.x);
                float2 hi = __half22float2(*(__half2*)&raw.y);
                a0 += lo.x * w; a1 += lo.y * w; a2 += hi.x * w; a3 += hi.y * w;
            }
        }
    }
    // combine the 4 edge-groups; all lanes end with full sums per sub
    a0 += __shfl_xor_sync(FULLM, a0, 8);  a0 += __shfl_xor_sync(FULLM, a0, 16);
    a1 += __shfl_xor_sync(FULLM, a1, 8);  a1 += __shfl_xor_sync(FULLM, a1, 16);
    a2 += __shfl_xor_sync(FULLM, a2, 8);  a2 += __shfl_xor_sync(FULLM, a2, 16);
    a3 += __shfl_xor_sync(FULLM, a3, 8);  a3 += __shfl_xor_sync(FULLM, a3, 16);

    // self-loop + bias + relu (all lanes compute; identical per sub)
    float di = d_dinv[n];
    float sl = di * di;
    uint2 raw = *(const uint2*)(h + (size_t)n * 32 + sub * 4);
    float2 lo = __half22float2(*(__half2*)&raw.x);
    float2 hi = __half22float2(*(__half2*)&raw.y);
    a0 += lo.x * sl; a1 += lo.y * sl; a2 += hi.x * sl; a3 += hi.y * sl;
    float v0 = fmaxf(a0 + sb2[sub * 4 + 0], 0.f);
    float v1 = fmaxf(a1 + sb2[sub * 4 + 1], 0.f);
    float v2 = fmaxf(a2 + sb2[sub * 4 + 2], 0.f);
    float v3 = fmaxf(a3 + sb2[sub * 4 + 3], 0.f);

    // classifier partials over this lane's 4 features
    float p[NC];
    #pragma unroll
    for (int c = 0; c < NC; c++) {
        p[c] = v0 * sWc[(sub * 4 + 0) * NC + c]
             + v1 * sWc[(sub * 4 + 1) * NC + c]
             + v2 * sWc[(sub * 4 + 2) * NC + c]
             + v3 * sWc[(sub * 4 + 3) * NC + c];
    }
    // reduce over the 8 subs (stays within each 8-lane group)
    #pragma unroll
    for (int off = 4; off >= 1; off >>= 1) {
        #pragma unroll
        for (int c = 0; c < NC; c++)
            p[c] += __shfl_xor_sync(FULLM, p[c], off);
    }
    if (lane == 0) {
        #pragma unroll
        for (int c = 0; c < NC; c++) p[c] += sbc[c];
        float m = p[0];
        #pragma unroll
        for (int c = 1; c < NC; c++) m = fmaxf(m, p[c]);
        float s = 0.f;
        #pragma unroll
        for (int c = 0; c < NC; c++) s += expf(p[c] - m);
        float lse = m + logf(s);
        #pragma unroll
        for (int c = 0; c < NC; c++)
            out[(size_t)n * NC + c] = p[c] - lse;
    }
}

// ---------------------------------------------------------------------------
extern "C" void kernel_launch(void* const* d_in, const int* in_sizes, int n_in,
                              void* d_out, int out_size) {
    const float* x  = (const float*)d_in[0];
    const void*  ei = d_in[1];
    const float* W1 = (const float*)d_in[2];
    const float* b1 = (const float*)d_in[3];
    const float* W2 = (const float*)d_in[4];
    const float* b2 = (const float*)d_in[5];
    const float* Wc = (const float*)d_in[6];
    const float* bc = (const float*)d_in[7];
    float* out = (float*)d_out;

    // ---- graph build (CSR via counting sort) ----
    k_zero_deg<<<(Nn + 255) / 256, 256>>>();
    k_detect<<<1, 32>>>((const int*)ei);
    k_deg<<<(Ee + 255) / 256, 256>>>(ei);
    k_scan1<<<NB_SCAN, SCAN_B>>>();
    k_scan2<<<1, 128>>>();
    k_scan3<<<(Nn + 255) / 256, 256>>>();
    k_scatter<<<(Ee + 255) / 256, 256>>>(ei);

    // ---- layer 1 ----
    k_gemm1<<<(Nn + 63) / 64, 256>>>(x, W1);
    k_agg1<<<(Nn + 7) / 8, 256>>>(b1);

    // ---- layer 2 + classifier ----
    k_gemm2<<<(Nn + 127) / 128, 256>>>(W2);
    k_final<<<(Nn + 7) / 8, 256>>>(b2, Wc, bc, out);
}